// round 14
// baseline (speedup 1.0000x reference)
#include <cuda_runtime.h>
#include <cuda_bf16.h>
#include <math_constants.h>

// Problem constants (shapes fixed by the dataset)
#define NN 50000
#define EE 1600000
#define FDIM 128
#define DENC 32
#define DEMB 12
#define NP24 24    // 48 fused output cols (32 enc + 12 emb + 4 pad), 2 per f32x2 pair
#define DH 128
#define PH_GRID 592   // pool_head blocks (deterministic partials sized to this)

// -------- device scratch (static: no allocation allowed) --------
__device__ float    g_s[NN];            // s[i] = relu(enc[i]) . w_inf[0:32]
__device__ float    g_inf[NN];          // influence logits
__device__ float    g_emb[NN * DEMB];   // emb[i] = nodes[i] @ W_emb + b_emb
__device__ float    g_part[PH_GRID * 13]; // per-block pooling partials (deterministic)
__device__ unsigned g_maxu;             // ordered-uint global max
__device__ unsigned g_done;             // pool_head last-block counter

// -------- packed f32x2 helpers --------
__device__ __forceinline__ unsigned long long pack2(float lo, float hi) {
    unsigned long long r;
    asm("mov.b64 %0, {%1, %2};" : "=l"(r) : "r"(__float_as_uint(lo)), "r"(__float_as_uint(hi)));
    return r;
}
__device__ __forceinline__ unsigned long long ffma2(unsigned long long a, unsigned long long b,
                                                    unsigned long long c) {
    unsigned long long d;
    asm("fma.rn.f32x2 %0, %1, %2, %3;" : "=l"(d) : "l"(a), "l"(b), "l"(c));
    return d;
}
__device__ __forceinline__ float lo32(unsigned long long v) { return __uint_as_float((unsigned)(v & 0xFFFFFFFFull)); }
__device__ __forceinline__ float hi32(unsigned long long v) { return __uint_as_float((unsigned)(v >> 32)); }

// ordered-float <-> uint for atomicMax
__device__ __forceinline__ unsigned fl_enc(float x) {
    unsigned b = __float_as_uint(x);
    return (b & 0x80000000u) ? ~b : (b | 0x80000000u);
}
__device__ __forceinline__ float fl_dec(unsigned u) {
    unsigned b = (u & 0x80000000u) ? (u ^ 0x80000000u) : ~u;
    return __uint_as_float(b);
}

// ============================================================================
// Kernel A: fused encode. 2 nodes x 6 column-pairs per thread (4-way column
// split). 256 thr/block. Biases folded into accumulator init. Also resets
// g_maxu / g_done for this replay (stream-ordered before consumers).
// ============================================================================
__global__ __launch_bounds__(256) void encode_kernel(
    const float* __restrict__ nodes,
    const float* __restrict__ W_enc,
    const float* __restrict__ b_enc,
    const float* __restrict__ W_inf, const float* __restrict__ b_inf,
    const float* __restrict__ W_emb,
    const float* __restrict__ b_emb,
    int n)
{
    __shared__ __align__(16) unsigned long long Wp[FDIM * NP24]; // [k][jpair]
    __shared__ unsigned long long bpair[NP24];
    __shared__ float sh_winf[33];
    __shared__ float sh_binf;
    __shared__ float s_sh[64 * 8];   // [nsub][node(2)][colg(4)]

    const int tid = threadIdx.x;

    if (blockIdx.x == 0) {
        if (tid == 0) g_maxu = 0u;
        if (tid == 1) g_done = 0u;
    }

    for (int idx = tid; idx < FDIM * NP24; idx += 256) {
        int k = idx / NP24, j = idx % NP24;
        int c0 = 2 * j, c1 = 2 * j + 1;
        float w0 = (c0 < DENC) ? W_enc[k * DENC + c0]
                 : (c0 < DENC + DEMB) ? W_emb[k * DEMB + (c0 - DENC)] : 0.f;
        float w1 = (c1 < DENC) ? W_enc[k * DENC + c1]
                 : (c1 < DENC + DEMB) ? W_emb[k * DEMB + (c1 - DENC)] : 0.f;
        Wp[idx] = ((unsigned long long)__float_as_uint(w1) << 32) | __float_as_uint(w0);
    }
    if (tid < NP24) {
        int c0 = 2 * tid, c1 = 2 * tid + 1;
        float v0 = (c0 < DENC) ? b_enc[c0] : (c0 < DENC + DEMB) ? b_emb[c0 - DENC] : 0.f;
        float v1 = (c1 < DENC) ? b_enc[c1] : (c1 < DENC + DEMB) ? b_emb[c1 - DENC] : 0.f;
        bpair[tid] = ((unsigned long long)__float_as_uint(v1) << 32) | __float_as_uint(v0);
    }
    if (tid < 33) sh_winf[tid] = W_inf[tid];
    if (tid == 0) sh_binf = b_inf[0];
    __syncthreads();

    const int colg = tid & 3;
    const int nsub = tid >> 2;
    const int base = blockIdx.x * 128;
    const int i0 = base + nsub;
    const int i1 = base + 64 + nsub;
    const bool v0 = (i0 < n), v1 = (i1 < n);
    const float4* r0 = (const float4*)(nodes + (v0 ? (size_t)i0 * FDIM : 0));
    const float4* r1 = (const float4*)(nodes + (v1 ? (size_t)i1 * FDIM : 0));
    const int jg = 6 * colg;

    unsigned long long acc0[6], acc1[6];
#pragma unroll
    for (int p = 0; p < 6; p++) { acc0[p] = bpair[jg + p]; acc1[p] = bpair[jg + p]; }

    float4 a0 = r0[0], a1 = r1[0];
    float last0 = 0.f, last1 = 0.f;
#pragma unroll 1
    for (int c = 0; c < FDIM / 4; c++) {
        float4 p0, p1;
        if (c < FDIM / 4 - 1) { p0 = r0[c + 1]; p1 = r1[c + 1]; }
#pragma unroll
        for (int q = 0; q < 4; q++) {
            float f0 = (q == 0) ? a0.x : (q == 1) ? a0.y : (q == 2) ? a0.z : a0.w;
            float f1 = (q == 0) ? a1.x : (q == 1) ? a1.y : (q == 2) ? a1.z : a1.w;
            unsigned long long x0 = pack2(f0, f0);
            unsigned long long x1 = pack2(f1, f1);
            const ulonglong2* w2 = (const ulonglong2*)&Wp[(4 * c + q) * NP24 + jg];
            ulonglong2 wa = w2[0], wb = w2[1], wc = w2[2];
            acc0[0] = ffma2(x0, wa.x, acc0[0]); acc1[0] = ffma2(x1, wa.x, acc1[0]);
            acc0[1] = ffma2(x0, wa.y, acc0[1]); acc1[1] = ffma2(x1, wa.y, acc1[1]);
            acc0[2] = ffma2(x0, wb.x, acc0[2]); acc1[2] = ffma2(x1, wb.x, acc1[2]);
            acc0[3] = ffma2(x0, wb.y, acc0[3]); acc1[3] = ffma2(x1, wb.y, acc1[3]);
            acc0[4] = ffma2(x0, wc.x, acc0[4]); acc1[4] = ffma2(x1, wc.x, acc1[4]);
            acc0[5] = ffma2(x0, wc.y, acc0[5]); acc1[5] = ffma2(x1, wc.y, acc1[5]);
        }
        if (c == FDIM / 4 - 1) { last0 = a0.w; last1 = a1.w; }
        a0 = p0; a1 = p1;
    }

    float s0 = 0.f, s1 = 0.f;
#pragma unroll
    for (int p = 0; p < 6; p++) {
        int j = jg + p;
        if (j < 16) {
            float wl = sh_winf[2 * j], wh = sh_winf[2 * j + 1];
            s0 = fmaf(fmaxf(lo32(acc0[p]), 0.f), wl, s0);
            s0 = fmaf(fmaxf(hi32(acc0[p]), 0.f), wh, s0);
            s1 = fmaf(fmaxf(lo32(acc1[p]), 0.f), wl, s1);
            s1 = fmaf(fmaxf(hi32(acc1[p]), 0.f), wh, s1);
        }
    }
    s_sh[nsub * 8 + colg]     = s0;
    s_sh[nsub * 8 + 4 + colg] = s1;
    __syncthreads();

    if (colg == 0 && v0) {
        float s = s_sh[nsub * 8 + 0] + s_sh[nsub * 8 + 1] + s_sh[nsub * 8 + 2] + s_sh[nsub * 8 + 3];
        g_s[i0] = s;
        g_inf[i0] = s + last0 * sh_winf[32] + sh_binf;
    }
    if (colg == 1 && v1) {
        float s = s_sh[nsub * 8 + 4] + s_sh[nsub * 8 + 5] + s_sh[nsub * 8 + 6] + s_sh[nsub * 8 + 7];
        g_s[i1] = s;
        g_inf[i1] = s + last1 * sh_winf[32] + sh_binf;
    }
    if (colg == 2) {
        float4 u; u.x = lo32(acc0[4]); u.y = hi32(acc0[4]); u.z = lo32(acc0[5]); u.w = hi32(acc0[5]);
        if (v0) ((float4*)(g_emb + (size_t)i0 * DEMB))[0] = u;
        u.x = lo32(acc1[4]); u.y = hi32(acc1[4]); u.z = lo32(acc1[5]); u.w = hi32(acc1[5]);
        if (v1) ((float4*)(g_emb + (size_t)i1 * DEMB))[0] = u;
    }
    if (colg == 3) {
        float4 u;
        if (v0) {
            float4* ep = (float4*)(g_emb + (size_t)i0 * DEMB);
            u.x = lo32(acc0[0]); u.y = hi32(acc0[0]); u.z = lo32(acc0[1]); u.w = hi32(acc0[1]); ep[1] = u;
            u.x = lo32(acc0[2]); u.y = hi32(acc0[2]); u.z = lo32(acc0[3]); u.w = hi32(acc0[3]); ep[2] = u;
        }
        if (v1) {
            float4* ep = (float4*)(g_emb + (size_t)i1 * DEMB);
            u.x = lo32(acc1[0]); u.y = hi32(acc1[0]); u.z = lo32(acc1[1]); u.w = hi32(acc1[1]); ep[1] = u;
            u.x = lo32(acc1[2]); u.y = hi32(acc1[2]); u.z = lo32(acc1[3]); u.w = hi32(acc1[3]); ep[2] = u;
        }
    }
}

// ============================================================================
// Kernel B: edge scatter. 8 consecutive edges / thread (2x int4 index loads),
// 512-thread blocks, multi-wave grid, REDG to g_inf.
// ============================================================================
__global__ __launch_bounds__(512) void scatter_kernel(
    const int* __restrict__ snd, const int* __restrict__ rcv, int e)
{
    const int t = blockIdx.x * blockDim.x + threadIdx.x;
    const int no = e >> 3;
    if (t < no) {
        int4 sa = __ldg(&((const int4*)snd)[2 * t]);
        int4 sb = __ldg(&((const int4*)snd)[2 * t + 1]);
        int4 ra = __ldg(&((const int4*)rcv)[2 * t]);
        int4 rb = __ldg(&((const int4*)rcv)[2 * t + 1]);
        float v0 = __ldg(&g_s[sa.x]);
        float v1 = __ldg(&g_s[sa.y]);
        float v2 = __ldg(&g_s[sa.z]);
        float v3 = __ldg(&g_s[sa.w]);
        float v4 = __ldg(&g_s[sb.x]);
        float v5 = __ldg(&g_s[sb.y]);
        float v6 = __ldg(&g_s[sb.z]);
        float v7 = __ldg(&g_s[sb.w]);
        atomicAdd(&g_inf[ra.x], v0);
        atomicAdd(&g_inf[ra.y], v1);
        atomicAdd(&g_inf[ra.z], v2);
        atomicAdd(&g_inf[ra.w], v3);
        atomicAdd(&g_inf[rb.x], v4);
        atomicAdd(&g_inf[rb.y], v5);
        atomicAdd(&g_inf[rb.z], v6);
        atomicAdd(&g_inf[rb.w], v7);
    } else if (t == no) {
        for (int i = no << 3; i < e; i++)
            atomicAdd(&g_inf[rcv[i]], __ldg(&g_s[snd[i]]));
    }
}

// ============================================================================
// Kernel C: global max of g_inf -> g_maxu (ordered-uint atomicMax)
// ============================================================================
__global__ __launch_bounds__(256) void max_kernel(int n)
{
    __shared__ float wm[8];
    const int t = threadIdx.x;
    const int stride = gridDim.x * blockDim.x;
    float m = -CUDART_INF_F;
    for (int i = blockIdx.x * blockDim.x + t; i < n; i += stride)
        m = fmaxf(m, g_inf[i]);
#pragma unroll
    for (int o = 16; o; o >>= 1) m = fmaxf(m, __shfl_xor_sync(0xFFFFFFFFu, m, o));
    if ((t & 31) == 0) wm[t >> 5] = m;
    __syncthreads();
    if (t == 0) {
        float mm = wm[0];
#pragma unroll
        for (int w = 1; w < 8; w++) mm = fmaxf(mm, wm[w]);
        atomicMax(&g_maxu, fl_enc(mm));
    }
}

// ============================================================================
// Kernel D: float softmax pooling -> deterministic per-block partials;
// last-done block reduces partials and runs the head MLP.
// ============================================================================
__global__ __launch_bounds__(256) void pool_head_kernel(
    const float* __restrict__ W1, const float* __restrict__ b1,
    const float* __restrict__ W2, const float* __restrict__ b2,
    const float* __restrict__ Wy, const float* __restrict__ by,
    const float* __restrict__ Wx, const float* __restrict__ bx,
    float* __restrict__ out, int n)
{
    __shared__ float red[8][13];
    __shared__ float sh_misc[16];   // [0]=last flag; [1..13]=summed accum
    __shared__ float h1[DH], h2[DH];

    const int t = threadIdx.x;
    const int bid = blockIdx.x;
    const int stride = gridDim.x * 256;
    const float gm = fl_dec(g_maxu);

    float sw = 0.f;
    float gc[DEMB];
#pragma unroll
    for (int j = 0; j < DEMB; j++) gc[j] = 0.f;

    for (int i = bid * 256 + t; i < n; i += stride) {
        float w = __expf(g_inf[i] - gm);
        const float4* ep = (const float4*)(g_emb + (size_t)i * DEMB);
        float4 e0 = ep[0], e1 = ep[1], e2 = ep[2];
        sw += w;
        gc[0]  = fmaf(w, e0.x, gc[0]);  gc[1]  = fmaf(w, e0.y, gc[1]);
        gc[2]  = fmaf(w, e0.z, gc[2]);  gc[3]  = fmaf(w, e0.w, gc[3]);
        gc[4]  = fmaf(w, e1.x, gc[4]);  gc[5]  = fmaf(w, e1.y, gc[5]);
        gc[6]  = fmaf(w, e1.z, gc[6]);  gc[7]  = fmaf(w, e1.w, gc[7]);
        gc[8]  = fmaf(w, e2.x, gc[8]);  gc[9]  = fmaf(w, e2.y, gc[9]);
        gc[10] = fmaf(w, e2.z, gc[10]); gc[11] = fmaf(w, e2.w, gc[11]);
    }
#pragma unroll
    for (int o = 16; o; o >>= 1) {
        sw += __shfl_xor_sync(0xFFFFFFFFu, sw, o);
#pragma unroll
        for (int j = 0; j < DEMB; j++) gc[j] += __shfl_xor_sync(0xFFFFFFFFu, gc[j], o);
    }
    if ((t & 31) == 0) {
        const int w = t >> 5;
#pragma unroll
        for (int j = 0; j < DEMB; j++) red[w][j] = gc[j];
        red[w][12] = sw;
    }
    __syncthreads();
    if (t < 13) {
        float acc = red[0][t];
#pragma unroll
        for (int w = 1; w < 8; w++) acc += red[w][t];
        g_part[bid * 13 + t] = acc;
    }
    __threadfence();
    __syncthreads();
    if (t == 0) {
        unsigned done = atomicAdd(&g_done, 1u);
        sh_misc[0] = (done == gridDim.x - 1) ? 1.f : 0.f;
    }
    __syncthreads();
    if (sh_misc[0] == 0.f) return;

    // ---- last-done block: reduce partials + head MLP ----
    __threadfence();
    {
        float pacc[13];
#pragma unroll
        for (int j = 0; j < 13; j++) pacc[j] = 0.f;
        for (int b = t; b < PH_GRID; b += 256) {
#pragma unroll
            for (int j = 0; j < 13; j++) pacc[j] += __ldcg(&g_part[b * 13 + j]);
        }
#pragma unroll
        for (int o = 16; o; o >>= 1)
#pragma unroll
            for (int j = 0; j < 13; j++) pacc[j] += __shfl_xor_sync(0xFFFFFFFFu, pacc[j], o);
        __syncthreads();
        if ((t & 31) == 0) {
            const int w = t >> 5;
#pragma unroll
            for (int j = 0; j < 13; j++) red[w][j] = pacc[j];
        }
        __syncthreads();
        if (t < 13) {
            float acc = red[0][t];
#pragma unroll
            for (int w = 1; w < 8; w++) acc += red[w][t];
            sh_misc[1 + t] = acc;
        }
        __syncthreads();
    }

    if (t < DH) {
        float a = b1[t];
#pragma unroll
        for (int j = 0; j < DEMB; j++) {
            float gj = sh_misc[1 + j] / sh_misc[13];
            a = fmaf(gj, W1[j * DH + t], a);
        }
        h1[t] = fmaxf(a, 0.f);
    }
    __syncthreads();
    if (t < DH) {
        float c = b2[t];
#pragma unroll 8
        for (int k = 0; k < DH; k++) c = fmaf(h1[k], W2[k * DH + t], c);
        h2[t] = fmaxf(c, 0.f);
    }
    __syncthreads();
    if (t < 4) {
        float o = bx[t];
        for (int k = 0; k < DH; k++) o = fmaf(h2[k], Wx[k * 4 + t], o);
        out[t] = o / 10.0f;
    }
    if (t == 4) {
        float o = by[0];
        for (int k = 0; k < DH; k++) o = fmaf(h2[k], Wy[k], o);
        out[4] = o;
    }
}

// ============================================================================
extern "C" void kernel_launch(void* const* d_in, const int* in_sizes, int n_in,
                              void* d_out, int out_size)
{
    const float* nodes  = (const float*)d_in[0];
    const int*   snd    = (const int*)d_in[1];
    const int*   rcv    = (const int*)d_in[2];
    const float* W_enc  = (const float*)d_in[3];
    const float* b_enc  = (const float*)d_in[4];
    const float* W_inf  = (const float*)d_in[5];
    const float* b_inf  = (const float*)d_in[6];
    const float* W_emb  = (const float*)d_in[7];
    const float* b_emb  = (const float*)d_in[8];
    const float* W1     = (const float*)d_in[9];
    const float* b1     = (const float*)d_in[10];
    const float* W2     = (const float*)d_in[11];
    const float* b2     = (const float*)d_in[12];
    const float* Wy     = (const float*)d_in[13];
    const float* by     = (const float*)d_in[14];
    const float* Wx     = (const float*)d_in[15];
    const float* bx     = (const float*)d_in[16];
    float* out = (float*)d_out;

    const int n = in_sizes[0] / FDIM;   // 50000
    const int e = in_sizes[1];          // 1600000

    // A: encode — 128 nodes / block (2 per thread, 4-way column split)
    int blocksA = (n + 127) / 128;
    encode_kernel<<<blocksA, 256>>>(nodes, W_enc, b_enc, W_inf, b_inf, W_emb, b_emb, n);

    // B: edge scatter — 8 edges / thread, 512-thread blocks
    int threadsB = (e >> 3) + 1;   // octet threads + 1 tail thread
    int blocksB = (threadsB + 511) / 512;
    scatter_kernel<<<blocksB, 512>>>(snd, rcv, e);

    // C: global max
    max_kernel<<<120, 256>>>(n);

    // D: softmax pooling + head (last-done block finishes)
    pool_head_kernel<<<PH_GRID, 256>>>(W1, b1, W2, b2, Wy, by, Wx, bx, out, n);
}

// round 15
// speedup vs baseline: 1.1431x; 1.1431x over previous
#include <cuda_runtime.h>
#include <cuda_bf16.h>
#include <math_constants.h>

// Problem constants (shapes fixed by the dataset)
#define NN 50000
#define EE 1600000
#define FDIM 128
#define DENC 32
#define DEMB 12
#define NP24 24    // 48 fused output cols (32 enc + 12 emb + 4 pad), 2 per f32x2 pair
#define DH 128

// -------- device scratch (static: no allocation allowed) --------
__device__ float    g_s[NN];            // s[i] = relu(enc[i]) . w_inf[0:32]
__device__ float    g_inf[NN];          // influence logits
__device__ float    g_emb[NN * DEMB];   // emb[i] = nodes[i] @ W_emb + b_emb
__device__ float    g_accum[16];        // [0:12]=sum w*emb, [12]=sum w
__device__ unsigned g_maxu;             // ordered-uint global max

// -------- packed f32x2 helpers --------
__device__ __forceinline__ unsigned long long pack2(float lo, float hi) {
    unsigned long long r;
    asm("mov.b64 %0, {%1, %2};" : "=l"(r) : "r"(__float_as_uint(lo)), "r"(__float_as_uint(hi)));
    return r;
}
__device__ __forceinline__ unsigned long long ffma2(unsigned long long a, unsigned long long b,
                                                    unsigned long long c) {
    unsigned long long d;
    asm("fma.rn.f32x2 %0, %1, %2, %3;" : "=l"(d) : "l"(a), "l"(b), "l"(c));
    return d;
}
__device__ __forceinline__ float lo32(unsigned long long v) { return __uint_as_float((unsigned)(v & 0xFFFFFFFFull)); }
__device__ __forceinline__ float hi32(unsigned long long v) { return __uint_as_float((unsigned)(v >> 32)); }

// ordered-float <-> uint for atomicMax
__device__ __forceinline__ unsigned fl_enc(float x) {
    unsigned b = __float_as_uint(x);
    return (b & 0x80000000u) ? ~b : (b | 0x80000000u);
}
__device__ __forceinline__ float fl_dec(unsigned u) {
    unsigned b = (u & 0x80000000u) ? (u ^ 0x80000000u) : ~u;
    return __uint_as_float(b);
}

// ============================================================================
// Kernel A: fused encode. 2 nodes x 6 column-pairs per thread (4-way column
// split). 256 thr/block. Biases folded into accumulator init. Also resets
// g_maxu / g_accum for this replay (stream-ordered before consumers).
// ============================================================================
__global__ __launch_bounds__(256) void encode_kernel(
    const float* __restrict__ nodes,
    const float* __restrict__ W_enc,
    const float* __restrict__ b_enc,
    const float* __restrict__ W_inf, const float* __restrict__ b_inf,
    const float* __restrict__ W_emb,
    const float* __restrict__ b_emb,
    int n)
{
    __shared__ __align__(16) unsigned long long Wp[FDIM * NP24]; // [k][jpair]
    __shared__ unsigned long long bpair[NP24];
    __shared__ float sh_winf[33];
    __shared__ float sh_binf;
    __shared__ float s_sh[64 * 8];   // [nsub][node(2)][colg(4)]

    const int tid = threadIdx.x;

    if (blockIdx.x == 0) {
        if (tid == 0) g_maxu = 0u;
        if (tid < 16) g_accum[tid] = 0.f;
    }

    for (int idx = tid; idx < FDIM * NP24; idx += 256) {
        int k = idx / NP24, j = idx % NP24;
        int c0 = 2 * j, c1 = 2 * j + 1;
        float w0 = (c0 < DENC) ? W_enc[k * DENC + c0]
                 : (c0 < DENC + DEMB) ? W_emb[k * DEMB + (c0 - DENC)] : 0.f;
        float w1 = (c1 < DENC) ? W_enc[k * DENC + c1]
                 : (c1 < DENC + DEMB) ? W_emb[k * DEMB + (c1 - DENC)] : 0.f;
        Wp[idx] = ((unsigned long long)__float_as_uint(w1) << 32) | __float_as_uint(w0);
    }
    if (tid < NP24) {
        int c0 = 2 * tid, c1 = 2 * tid + 1;
        float v0 = (c0 < DENC) ? b_enc[c0] : (c0 < DENC + DEMB) ? b_emb[c0 - DENC] : 0.f;
        float v1 = (c1 < DENC) ? b_enc[c1] : (c1 < DENC + DEMB) ? b_emb[c1 - DENC] : 0.f;
        bpair[tid] = ((unsigned long long)__float_as_uint(v1) << 32) | __float_as_uint(v0);
    }
    if (tid < 33) sh_winf[tid] = W_inf[tid];
    if (tid == 0) sh_binf = b_inf[0];
    __syncthreads();

    const int colg = tid & 3;
    const int nsub = tid >> 2;
    const int base = blockIdx.x * 128;
    const int i0 = base + nsub;
    const int i1 = base + 64 + nsub;
    const bool v0 = (i0 < n), v1 = (i1 < n);
    const float4* r0 = (const float4*)(nodes + (v0 ? (size_t)i0 * FDIM : 0));
    const float4* r1 = (const float4*)(nodes + (v1 ? (size_t)i1 * FDIM : 0));
    const int jg = 6 * colg;

    unsigned long long acc0[6], acc1[6];
#pragma unroll
    for (int p = 0; p < 6; p++) { acc0[p] = bpair[jg + p]; acc1[p] = bpair[jg + p]; }

    float4 a0 = r0[0], a1 = r1[0];
    float last0 = 0.f, last1 = 0.f;
#pragma unroll 1
    for (int c = 0; c < FDIM / 4; c++) {
        float4 p0, p1;
        if (c < FDIM / 4 - 1) { p0 = r0[c + 1]; p1 = r1[c + 1]; }
#pragma unroll
        for (int q = 0; q < 4; q++) {
            float f0 = (q == 0) ? a0.x : (q == 1) ? a0.y : (q == 2) ? a0.z : a0.w;
            float f1 = (q == 0) ? a1.x : (q == 1) ? a1.y : (q == 2) ? a1.z : a1.w;
            unsigned long long x0 = pack2(f0, f0);
            unsigned long long x1 = pack2(f1, f1);
            const ulonglong2* w2 = (const ulonglong2*)&Wp[(4 * c + q) * NP24 + jg];
            ulonglong2 wa = w2[0], wb = w2[1], wc = w2[2];
            acc0[0] = ffma2(x0, wa.x, acc0[0]); acc1[0] = ffma2(x1, wa.x, acc1[0]);
            acc0[1] = ffma2(x0, wa.y, acc0[1]); acc1[1] = ffma2(x1, wa.y, acc1[1]);
            acc0[2] = ffma2(x0, wb.x, acc0[2]); acc1[2] = ffma2(x1, wb.x, acc1[2]);
            acc0[3] = ffma2(x0, wb.y, acc0[3]); acc1[3] = ffma2(x1, wb.y, acc1[3]);
            acc0[4] = ffma2(x0, wc.x, acc0[4]); acc1[4] = ffma2(x1, wc.x, acc1[4]);
            acc0[5] = ffma2(x0, wc.y, acc0[5]); acc1[5] = ffma2(x1, wc.y, acc1[5]);
        }
        if (c == FDIM / 4 - 1) { last0 = a0.w; last1 = a1.w; }
        a0 = p0; a1 = p1;
    }

    float s0 = 0.f, s1 = 0.f;
#pragma unroll
    for (int p = 0; p < 6; p++) {
        int j = jg + p;
        if (j < 16) {
            float wl = sh_winf[2 * j], wh = sh_winf[2 * j + 1];
            s0 = fmaf(fmaxf(lo32(acc0[p]), 0.f), wl, s0);
            s0 = fmaf(fmaxf(hi32(acc0[p]), 0.f), wh, s0);
            s1 = fmaf(fmaxf(lo32(acc1[p]), 0.f), wl, s1);
            s1 = fmaf(fmaxf(hi32(acc1[p]), 0.f), wh, s1);
        }
    }
    s_sh[nsub * 8 + colg]     = s0;
    s_sh[nsub * 8 + 4 + colg] = s1;
    __syncthreads();

    if (colg == 0 && v0) {
        float s = s_sh[nsub * 8 + 0] + s_sh[nsub * 8 + 1] + s_sh[nsub * 8 + 2] + s_sh[nsub * 8 + 3];
        g_s[i0] = s;
        g_inf[i0] = s + last0 * sh_winf[32] + sh_binf;
    }
    if (colg == 1 && v1) {
        float s = s_sh[nsub * 8 + 4] + s_sh[nsub * 8 + 5] + s_sh[nsub * 8 + 6] + s_sh[nsub * 8 + 7];
        g_s[i1] = s;
        g_inf[i1] = s + last1 * sh_winf[32] + sh_binf;
    }
    if (colg == 2) {
        float4 u; u.x = lo32(acc0[4]); u.y = hi32(acc0[4]); u.z = lo32(acc0[5]); u.w = hi32(acc0[5]);
        if (v0) ((float4*)(g_emb + (size_t)i0 * DEMB))[0] = u;
        u.x = lo32(acc1[4]); u.y = hi32(acc1[4]); u.z = lo32(acc1[5]); u.w = hi32(acc1[5]);
        if (v1) ((float4*)(g_emb + (size_t)i1 * DEMB))[0] = u;
    }
    if (colg == 3) {
        float4 u;
        if (v0) {
            float4* ep = (float4*)(g_emb + (size_t)i0 * DEMB);
            u.x = lo32(acc0[0]); u.y = hi32(acc0[0]); u.z = lo32(acc0[1]); u.w = hi32(acc0[1]); ep[1] = u;
            u.x = lo32(acc0[2]); u.y = hi32(acc0[2]); u.z = lo32(acc0[3]); u.w = hi32(acc0[3]); ep[2] = u;
        }
        if (v1) {
            float4* ep = (float4*)(g_emb + (size_t)i1 * DEMB);
            u.x = lo32(acc1[0]); u.y = hi32(acc1[0]); u.z = lo32(acc1[1]); u.w = hi32(acc1[1]); ep[1] = u;
            u.x = lo32(acc1[2]); u.y = hi32(acc1[2]); u.z = lo32(acc1[3]); u.w = hi32(acc1[3]); ep[2] = u;
        }
    }
}

// ============================================================================
// Kernel B: edge scatter. 4 consecutive edges / thread (int4 index loads),
// multi-wave grid, REDG (atomicAdd no-return) to g_inf.  (R13-validated)
// ============================================================================
__global__ __launch_bounds__(256) void scatter_kernel(
    const int* __restrict__ snd, const int* __restrict__ rcv, int e)
{
    int t = blockIdx.x * blockDim.x + threadIdx.x;
    int base = t * 4;
    if (base + 3 < e) {
        int4 aa = __ldg(&((const int4*)snd)[t]);
        int4 bb = __ldg(&((const int4*)rcv)[t]);
        float v0 = __ldg(&g_s[aa.x]);
        float v1 = __ldg(&g_s[aa.y]);
        float v2 = __ldg(&g_s[aa.z]);
        float v3 = __ldg(&g_s[aa.w]);
        atomicAdd(&g_inf[bb.x], v0);
        atomicAdd(&g_inf[bb.y], v1);
        atomicAdd(&g_inf[bb.z], v2);
        atomicAdd(&g_inf[bb.w], v3);
    } else {
        for (int i = base; i < e; i++) atomicAdd(&g_inf[rcv[i]], __ldg(&g_s[snd[i]]));
    }
}

// ============================================================================
// Kernel C: global max of g_inf -> g_maxu (ordered-uint atomicMax)
// ============================================================================
__global__ __launch_bounds__(256) void max_kernel(int n)
{
    __shared__ float wm[8];
    const int t = threadIdx.x;
    const int stride = gridDim.x * blockDim.x;
    float m = -CUDART_INF_F;
    for (int i = blockIdx.x * blockDim.x + t; i < n; i += stride)
        m = fmaxf(m, g_inf[i]);
#pragma unroll
    for (int o = 16; o; o >>= 1) m = fmaxf(m, __shfl_xor_sync(0xFFFFFFFFu, m, o));
    if ((t & 31) == 0) wm[t >> 5] = m;
    __syncthreads();
    if (t == 0) {
        float mm = wm[0];
#pragma unroll
        for (int w = 1; w < 8; w++) mm = fmaxf(mm, wm[w]);
        atomicMax(&g_maxu, fl_enc(mm));
    }
}

// ============================================================================
// Kernel D: float softmax pooling -> g_accum via 13 global atomicAdds/block
// ============================================================================
__global__ __launch_bounds__(256) void pool_kernel(int n)
{
    __shared__ float red[8][13];
    const int t = threadIdx.x;
    const int stride = gridDim.x * blockDim.x;
    const float gm = fl_dec(g_maxu);

    float sw = 0.f;
    float gc[DEMB];
#pragma unroll
    for (int j = 0; j < DEMB; j++) gc[j] = 0.f;

    for (int i = blockIdx.x * blockDim.x + t; i < n; i += stride) {
        float w = __expf(g_inf[i] - gm);
        const float4* ep = (const float4*)(g_emb + (size_t)i * DEMB);
        float4 e0 = ep[0], e1 = ep[1], e2 = ep[2];
        sw += w;
        gc[0]  = fmaf(w, e0.x, gc[0]);  gc[1]  = fmaf(w, e0.y, gc[1]);
        gc[2]  = fmaf(w, e0.z, gc[2]);  gc[3]  = fmaf(w, e0.w, gc[3]);
        gc[4]  = fmaf(w, e1.x, gc[4]);  gc[5]  = fmaf(w, e1.y, gc[5]);
        gc[6]  = fmaf(w, e1.z, gc[6]);  gc[7]  = fmaf(w, e1.w, gc[7]);
        gc[8]  = fmaf(w, e2.x, gc[8]);  gc[9]  = fmaf(w, e2.y, gc[9]);
        gc[10] = fmaf(w, e2.z, gc[10]); gc[11] = fmaf(w, e2.w, gc[11]);
    }
#pragma unroll
    for (int o = 16; o; o >>= 1) {
        sw += __shfl_xor_sync(0xFFFFFFFFu, sw, o);
#pragma unroll
        for (int j = 0; j < DEMB; j++) gc[j] += __shfl_xor_sync(0xFFFFFFFFu, gc[j], o);
    }
    if ((t & 31) == 0) {
        const int w = t >> 5;
#pragma unroll
        for (int j = 0; j < DEMB; j++) red[w][j] = gc[j];
        red[w][12] = sw;
    }
    __syncthreads();
    if (t < 13) {
        float acc = red[0][t];
#pragma unroll
        for (int w = 1; w < 8; w++) acc += red[w][t];
        atomicAdd(&g_accum[t], acc);
    }
}

// ============================================================================
// Kernel E: head MLP (single block, 128 threads). W2 preloaded into smem
// cooperatively (coalesced) to avoid cold-DRAM stalls in the FMA loops.
// ============================================================================
__global__ __launch_bounds__(DH) void head_kernel(
    const float* __restrict__ W1, const float* __restrict__ b1,
    const float* __restrict__ W2, const float* __restrict__ b2,
    const float* __restrict__ Wy, const float* __restrict__ by,
    const float* __restrict__ Wx, const float* __restrict__ bx,
    float* __restrict__ out)
{
    __shared__ float g[DEMB];
    __shared__ float h1[DH], h2[DH];
    __shared__ float sW2[DH * DH];        // 64KB
    __shared__ float sWx[DH * 4];
    __shared__ float sWy[DH];
    const int t = threadIdx.x;

    // cooperative preloads (coalesced float4)
    {
        const float4* src = (const float4*)W2;
        float4* dst = (float4*)sW2;
#pragma unroll
        for (int i = 0; i < (DH * DH) / 4 / DH; i++)   // 32 iters
            dst[i * DH + t] = src[i * DH + t];
        ((float4*)sWx)[t] = ((const float4*)Wx)[t];
        sWy[t] = Wy[t];
    }
    if (t < DEMB) g[t] = g_accum[t] / g_accum[12];
    __syncthreads();

    float a = b1[t];
#pragma unroll
    for (int j = 0; j < DEMB; j++) a = fmaf(g[j], W1[j * DH + t], a);
    h1[t] = fmaxf(a, 0.f);
    __syncthreads();

    float c = b2[t];
#pragma unroll 8
    for (int k = 0; k < DH; k++) c = fmaf(h1[k], sW2[k * DH + t], c);
    h2[t] = fmaxf(c, 0.f);
    __syncthreads();

    if (t < 4) {
        float o = bx[t];
#pragma unroll 8
        for (int k = 0; k < DH; k++) o = fmaf(h2[k], sWx[k * 4 + t], o);
        out[t] = o / 10.0f;
    }
    if (t == 4) {
        float o = by[0];
#pragma unroll 8
        for (int k = 0; k < DH; k++) o = fmaf(h2[k], sWy[k], o);
        out[4] = o;
    }
}

// ============================================================================
extern "C" void kernel_launch(void* const* d_in, const int* in_sizes, int n_in,
                              void* d_out, int out_size)
{
    const float* nodes  = (const float*)d_in[0];
    const int*   snd    = (const int*)d_in[1];
    const int*   rcv    = (const int*)d_in[2];
    const float* W_enc  = (const float*)d_in[3];
    const float* b_enc  = (const float*)d_in[4];
    const float* W_inf  = (const float*)d_in[5];
    const float* b_inf  = (const float*)d_in[6];
    const float* W_emb  = (const float*)d_in[7];
    const float* b_emb  = (const float*)d_in[8];
    const float* W1     = (const float*)d_in[9];
    const float* b1     = (const float*)d_in[10];
    const float* W2     = (const float*)d_in[11];
    const float* b2     = (const float*)d_in[12];
    const float* Wy     = (const float*)d_in[13];
    const float* by     = (const float*)d_in[14];
    const float* Wx     = (const float*)d_in[15];
    const float* bx     = (const float*)d_in[16];
    float* out = (float*)d_out;

    const int n = in_sizes[0] / FDIM;   // 50000
    const int e = in_sizes[1];          // 1600000

    // A: encode — 128 nodes / block (2 per thread, 4-way column split)
    int blocksA = (n + 127) / 128;
    encode_kernel<<<blocksA, 256>>>(nodes, W_enc, b_enc, W_inf, b_inf, W_emb, b_emb, n);

    // B: edge scatter — 4 edges / thread, multi-wave (R13-validated)
    int threadsB = (e + 3) / 4;
    int blocksB = (threadsB + 255) / 256;
    scatter_kernel<<<blocksB, 256>>>(snd, rcv, e);

    // C: global max
    max_kernel<<<120, 256>>>(n);

    // D: softmax pooling (2 CTAs/SM)
    pool_kernel<<<296, 256>>>(n);

    // E: head
    head_kernel<<<1, DH>>>(W1, b1, W2, b2, Wy, by, Wx, bx, out);
}